// round 9
// baseline (speedup 1.0000x reference)
#include <cuda_runtime.h>
#include <math.h>

// ChamferLoss: bs=4, npts=4096, dim=3.
// Fused single pass: each distance^2 computed ONCE; row mins (per y) in registers,
// col mins (per x) via warp bfly-reduce -> per-warp smem arrays (each warp sees each
// x exactly once -> plain store). dist^2 = ||y||^2 + ||x||^2 - 2 x.y via packed f32x2.
// Grid 8 xtiles x 4 ytiles x 4 batches = 128 blocks = one balanced wave.
// Distributed finishers via self-resetting counters (deterministic, graph-replayable).

#define NPTS 4096
#define BS   4
#define TPB  256
#define NWARP (TPB / 32)             // 8
#define XT   512                     // x-tile (cols) per block
#define YT   1024                    // y-tile (rows) per block
#define TY   4                       // y's per thread (TY*TPB = YT)
#define XTILES (NPTS / XT)           // 8
#define YTILES (NPTS / YT)           // 4
#define BPB  (XTILES * YTILES)       // 32 blocks per batch

__device__ float g_rowpart[BS * NPTS * XTILES];  // [b][y][xt]
__device__ float g_colpart[BS * NPTS * YTILES];  // [b][x][yt]
__device__ float g_bsum[BS];
__device__ unsigned int g_bc[BS];                // zero-init, self-resetting
__device__ unsigned int g_fc;                    // zero-init, self-resetting

__device__ __forceinline__ unsigned long long bcast2(float f) {
    unsigned long long v;
    asm("mov.b64 %0, {%1, %1};" : "=l"(v) : "r"(__float_as_uint(f)));
    return v;
}
__device__ __forceinline__ void unpack2(unsigned long long v, float& a, float& b) {
    unsigned lo, hi;
    asm("mov.b64 {%0, %1}, %2;" : "=r"(lo), "=r"(hi) : "l"(v));
    a = __uint_as_float(lo); b = __uint_as_float(hi);
}
__device__ __forceinline__ unsigned long long fma2(unsigned long long a,
                                                   unsigned long long b,
                                                   unsigned long long c) {
    unsigned long long d;
    asm("fma.rn.f32x2 %0, %1, %2, %3;" : "=l"(d) : "l"(a), "l"(b), "l"(c));
    return d;
}
__device__ __forceinline__ unsigned long long add2(unsigned long long a,
                                                   unsigned long long b) {
    unsigned long long d;
    asm("add.rn.f32x2 %0, %1, %2;" : "=l"(d) : "l"(a), "l"(b));
    return d;
}

__global__ __launch_bounds__(TPB, 1) void chamfer_fused(
    const float* __restrict__ x, const float* __restrict__ y, float* __restrict__ out)
{
    __shared__ float sx[XT * 4];             // 8 KB: groups of 4 x: [-2xx|-2xy|-2xz|xsq]
    __shared__ float scol[NWARP * XT];       // 16 KB: per-warp col mins
    __shared__ float red[NWARP];
    __shared__ int   s_last;

    const int tid  = threadIdx.x;
    const int lane = tid & 31;
    const int w    = tid >> 5;
    const int xt   = blockIdx.x;             // 0..XTILES-1
    const int yt   = blockIdx.y;             // 0..YTILES-1
    const int b    = blockIdx.z;             // 0..BS-1

    const float* __restrict__ xb = x + ((size_t)b * NPTS + (size_t)xt * XT) * 3;
    const float* __restrict__ yb = y + (size_t)b * NPTS * 3;

    // Stage x-tile: -2x (SoA groups of 4) and ||x||^2.
    #pragma unroll 2
    for (int i = tid; i < XT; i += TPB) {
        float xx = xb[3 * i + 0];
        float xy = xb[3 * i + 1];
        float xz = xb[3 * i + 2];
        float* base = sx + ((i >> 2) << 4) + (i & 3);
        base[0]  = -2.0f * xx;
        base[4]  = -2.0f * xy;
        base[8]  = -2.0f * xz;
        base[12] = fmaf(xx, xx, fmaf(xy, xy, xz * xz));
    }

    // TY=4 y-points per thread.
    unsigned long long by0[TY], by1[TY], by2[TY], ysq2[TY];
    #pragma unroll
    for (int k = 0; k < TY; ++k) {
        const float* yp = yb + (size_t)(yt * YT + k * TPB + tid) * 3;
        float ya = yp[0], yc = yp[1], yd = yp[2];
        by0[k] = bcast2(ya); by1[k] = bcast2(yc); by2[k] = bcast2(yd);
        ysq2[k] = bcast2(fmaf(ya, ya, fmaf(yc, yc, yd * yd)));
    }

    __syncthreads();

    const ulonglong2* __restrict__ sp = (const ulonglong2*)sx;
    float rowm[TY];
    #pragma unroll
    for (int k = 0; k < TY; ++k) rowm[k] = 3.402823466e+38f;

    #pragma unroll 2
    for (int g = 0; g < XT / 4; ++g) {
        ulonglong2 X = sp[g * 4 + 0];
        ulonglong2 Y = sp[g * 4 + 1];
        ulonglong2 Z = sp[g * 4 + 2];
        ulonglong2 H = sp[g * 4 + 3];

        float cm0, cm1, cm2, cm3;
        #pragma unroll
        for (int k = 0; k < TY; ++k) {
            unsigned long long h0 = add2(H.x, ysq2[k]);
            unsigned long long h1 = add2(H.y, ysq2[k]);
            unsigned long long t0 = fma2(by2[k], Z.x, h0);
            t0 = fma2(by1[k], Y.x, t0);
            t0 = fma2(by0[k], X.x, t0);
            unsigned long long t1 = fma2(by2[k], Z.y, h1);
            t1 = fma2(by1[k], Y.y, t1);
            t1 = fma2(by0[k], X.y, t1);
            float a0, a1, a2, a3;
            unpack2(t0, a0, a1);
            unpack2(t1, a2, a3);
            rowm[k] = fminf(rowm[k], fminf(fminf(a0, a1), fminf(a2, a3)));
            if (k == 0) { cm0 = a0; cm1 = a1; cm2 = a2; cm3 = a3; }
            else {
                cm0 = fminf(cm0, a0); cm1 = fminf(cm1, a1);
                cm2 = fminf(cm2, a2); cm3 = fminf(cm3, a3);
            }
        }
        // Warp-wide col reduce (bfly keeps value in all lanes).
        #pragma unroll
        for (int off = 16; off; off >>= 1) {
            cm0 = fminf(cm0, __shfl_xor_sync(0xFFFFFFFFu, cm0, off));
            cm1 = fminf(cm1, __shfl_xor_sync(0xFFFFFFFFu, cm1, off));
            cm2 = fminf(cm2, __shfl_xor_sync(0xFFFFFFFFu, cm2, off));
            cm3 = fminf(cm3, __shfl_xor_sync(0xFFFFFFFFu, cm3, off));
        }
        if (lane == 0) {
            float* c = scol + w * XT + g * 4;
            c[0] = cm0; c[1] = cm1; c[2] = cm2; c[3] = cm3;
        }
    }

    __syncthreads();

    // Row partials -> global.
    #pragma unroll
    for (int k = 0; k < TY; ++k) {
        int yi = yt * YT + k * TPB + tid;
        g_rowpart[((size_t)b * NPTS + yi) * XTILES + xt] = rowm[k];
    }
    // Col partials: min over 8 warp arrays -> global.
    #pragma unroll 2
    for (int j = tid; j < XT; j += TPB) {
        float m = scol[j];
        #pragma unroll
        for (int ww = 1; ww < NWARP; ++ww) m = fminf(m, scol[ww * XT + j]);
        g_colpart[((size_t)b * NPTS + (xt * XT + j)) * YTILES + yt] = m;
    }

    // ---- Per-batch finisher ----
    __threadfence();
    if (tid == 0)
        s_last = (atomicAdd(&g_bc[b], 1u) == BPB - 1) ? 1 : 0;
    __syncthreads();

    if (s_last) {
        if (tid == 0) g_bc[b] = 0;       // self-reset
        __threadfence();
        float acc = 0.0f;
        // Rows: 4096 y, XTILES=8 partials each (2x float4).
        #pragma unroll 4
        for (int i = tid; i < NPTS; i += TPB) {
            const float4* p = (const float4*)&g_rowpart[((size_t)b * NPTS + i) * XTILES];
            float4 A = __ldcg(p), B = __ldcg(p + 1);
            float m = fminf(fminf(fminf(A.x, A.y), fminf(A.z, A.w)),
                            fminf(fminf(B.x, B.y), fminf(B.z, B.w)));
            acc += sqrtf(1e-6f + m);
        }
        // Cols: 4096 x, YTILES=4 partials each (1x float4).
        #pragma unroll 4
        for (int i = tid; i < NPTS; i += TPB) {
            float4 A = __ldcg((const float4*)&g_colpart[((size_t)b * NPTS + i) * YTILES]);
            acc += sqrtf(1e-6f + fminf(fminf(A.x, A.y), fminf(A.z, A.w)));
        }
        #pragma unroll
        for (int off = 16; off; off >>= 1)
            acc += __shfl_down_sync(0xFFFFFFFFu, acc, off);
        if (lane == 0) red[w] = acc;
        __syncthreads();
        if (tid == 0) {
            float t = 0.0f;
            #pragma unroll
            for (int i = 0; i < NWARP; ++i) t += red[i];
            g_bsum[b] = t;
            __threadfence();
            if (atomicAdd(&g_fc, 1u) == BS - 1) {
                volatile float* gs = g_bsum;
                float tot = gs[0] + gs[1] + gs[2] + gs[3];
                out[0] = tot * (1.0f / 16384.0f);   // (S1 + S2) / (BS * NPTS)
                g_fc = 0;                            // self-reset
            }
        }
    }
}

extern "C" void kernel_launch(void* const* d_in, const int* in_sizes, int n_in,
                              void* d_out, int out_size)
{
    const float* x = (const float*)d_in[0];
    const float* y = (const float*)d_in[1];
    float* out = (float*)d_out;

    chamfer_fused<<<dim3(XTILES, YTILES, BS), TPB>>>(x, y, out);
}